// round 11
// baseline (speedup 1.0000x reference)
#include <cuda_runtime.h>
#include <cuda_fp16.h>
#include <cstdint>

// out[b,i,j,m] = tanh( sum_d v1[b,i,d] * kernel[m,d] * v2[b,j,d] )
#define PB   64
#define PT1  128
#define PT2  160
#define PD   768
#define PM   64

#define NS16     48                   // 16-wide k-slices total
#define KSC      4                    // slices per chunk (K=64)
#define NCHUNK   (NS16 / KSC)         // 12
#define NS       3                    // v2 pipeline stages
#define NT       320                  // 10 warps
#define I_PER    2

#define PRSTR    320                  // v2 pair-row stride per chunk (256B data + 64B pad; 320/16 % 8 == 4 -> conflict-free LDS.128)
#define STG_V2   (80 * PRSTR)         // 25600
#define SLICE_B  2176                 // B' bytes per k16 slice (4 qc x 544)
#define BP_II    (KSC * SLICE_B)      // 8704 per ii
#define BP_BYTES (I_PER * BP_II)      // 17408
#define V1T      3072                 // v1 table: 2 ii x 192 float2
#define BP_OFF   (V1T + NS * STG_V2)  // 79872
#define SMEM_TOTAL (BP_OFF + BP_BYTES) // 97280

#define V2HN (PB * 80 * NS16 * 4)     // 983040 float4 entries
#define KHN  (NS16 * 4 * PM)          // 12288 float2 slots

// ---- device-global fp16-prepped operands (layouts unchanged from R10) ----
// g_v2h[((b*80+pr)*48+s)*4+qc] = {h2(v2[j][d0],v2[j][d0+1]), h2(v2[j8][..]), h2(v2[j][d0+8],..), h2(v2[j8][d0+8],..)}
//   j = (pr>>3)*16 + (pr&7), j8 = j+8, d0 = s*16 + 2*qc
__device__ __align__(16) float4 g_v2h[V2HN];
// g_kh[s*272 + qc*68 + m] = {h2(k[m][d0],k[m][d0+1]), h2(k[m][d0+8],k[m][d0+9])}
__device__ __align__(16) float2 g_kh[NS16 * 272];

__device__ __forceinline__ float fast_tanh(float x) {
    float ax = fabsf(x);
    float e  = __expf(-2.0f * ax);
    float r  = __fdividef(1.0f - e, 1.0f + e);
    return copysignf(r, x);
}
__device__ __forceinline__ uint32_t s2u(const void* p) {
    uint32_t a;
    asm("{ .reg .u64 t; cvta.to.shared.u64 t, %1; cvt.u32.u64 %0, t; }" : "=r"(a) : "l"(p));
    return a;
}
__device__ __forceinline__ void cpa16(uint32_t dst, const void* src) {
    asm volatile("cp.async.cg.shared.global [%0], [%1], 16;" :: "r"(dst), "l"(src));
}
__device__ __forceinline__ uint32_t h2pack(float x, float y) {
    __half2 h = __floats2half2_rn(x, y);
    return *(uint32_t*)&h;
}
__device__ __forceinline__ uint32_t hmul2(uint32_t a, uint32_t b) {
    uint32_t d;
    asm("mul.rn.f16x2 %0, %1, %2;" : "=r"(d) : "r"(a), "r"(b));
    return d;
}

// ---- prep: fp16-convert + permute v2 and kernel (unchanged from R10) ----
__global__ void prep_all(const float* __restrict__ v2, const float* __restrict__ kern) {
    int t = blockIdx.x * blockDim.x + threadIdx.x;
    if (t < V2HN) {
        int qc = t & 3;
        int t2 = t >> 2;
        int s  = t2 % NS16;
        int pr = (t2 / NS16) % 80;
        int b  = t2 / (NS16 * 80);
        int j  = (pr >> 3) * 16 + (pr & 7);
        int d0 = s * 16 + 2 * qc;
        const float* p0 = v2 + ((size_t)(b * PT2 + j) * PD + d0);
        const float* p8 = p0 + 8 * PD;
        float4 o;
        o.x = __uint_as_float(h2pack(p0[0], p0[1]));
        o.y = __uint_as_float(h2pack(p8[0], p8[1]));
        o.z = __uint_as_float(h2pack(p0[8], p0[9]));
        o.w = __uint_as_float(h2pack(p8[8], p8[9]));
        g_v2h[t] = o;
    } else if (t < V2HN + KHN) {
        int u  = t - V2HN;
        int m  = u & 63;
        int qc = (u >> 6) & 3;
        int s  = u >> 8;
        int d0 = s * 16 + 2 * qc;
        const float* kp = kern + (size_t)m * PD + d0;
        float2 o;
        o.x = __uint_as_float(h2pack(kp[0], kp[1]));
        o.y = __uint_as_float(h2pack(kp[8], kp[9]));
        g_kh[s * 272 + qc * 68 + m] = o;
    }
}

extern __shared__ char dynsmem[];

// stage one chunk of v2 (4 k16 slices): 1280 float4
__device__ __forceinline__ void prefetch_v2(uint32_t stg, int b, int s0, int tid) {
#pragma unroll
    for (int it = 0; it < 4; it++) {               // 1280 = 4 * NT
        int t  = tid + it * NT;
        int pr = t >> 4, r = t & 15;               // r = s'*4 + qc
        cpa16(stg + pr * PRSTR + r * 16,
              g_v2h + (((size_t)b * 80 + pr) * NS16 + s0 + (r >> 2)) * 4 + (r & 3));
    }
}

__global__ __launch_bounds__(NT, 2)
void mpcos_main(const float* __restrict__ v1, float* __restrict__ out)
{
    const uint32_t sb = s2u(dynsmem);
    const int tid  = threadIdx.x;
    const int w    = tid >> 5, lane = tid & 31;
    const int qrow = lane >> 2, qc = lane & 3;
    const int ii   = w / 5, j5 = w % 5;            // warp = (ii, j32-tile)
    const int b    = blockIdx.y;
    const int i0   = blockIdx.x * I_PER;

    const float* v1b = v1 + ((size_t)b * PT1 + i0) * PD;

    // ---- v1 fp16 pair table: slot = i*192 + s*4 + q -> {h2(d0,d0+1), h2(d0+8,d0+9)} ----
    for (int t = tid; t < I_PER * 192; t += NT) {  // strided: 384 > NT
        int iv = (t >= 192) ? 1 : 0;
        int r  = t - iv * 192;
        int s  = r >> 2, q = r & 3;
        int d0 = s * 16 + 2 * q;
        const float* vp = v1b + (size_t)iv * PD + d0;
        float2 o;
        o.x = __uint_as_float(h2pack(vp[0], vp[1]));
        o.y = __uint_as_float(h2pack(vp[8], vp[9]));
        *(float2*)(dynsmem + (size_t)t * 8) = o;
    }

    prefetch_v2(sb + V1T, b, 0, tid);
    asm volatile("cp.async.commit_group;" ::: "memory");
    prefetch_v2(sb + V1T + STG_V2, b, KSC, tid);
    asm volatile("cp.async.commit_group;" ::: "memory");

    float acc[2][8][4] = {};                       // [jsub][nt][4]

    const uint32_t aoff = (uint32_t)(((2 * j5) * 8 + qrow) * PRSTR + qc * 16);
    const uint32_t bpo  = (uint32_t)(BP_OFF + ii * BP_II + qc * 544 + qrow * 8);

    for (int c = 0; c < NCHUNK; c++) {
        if (c < NCHUNK - 1)
            asm volatile("cp.async.wait_group 1;" ::: "memory");  // chunk c arrived
        else
            asm volatile("cp.async.wait_group 0;" ::: "memory");
        __syncthreads();                            // chunk c-1 + B'(c-1) fully consumed

        if (c + 2 < NCHUNK) {
            prefetch_v2(sb + V1T + ((c + 2) % NS) * STG_V2, b, (c + 2) * KSC, tid);
            asm volatile("cp.async.commit_group;" ::: "memory");
        }

        // ---- build B'(c) = kern * v1 cooperatively: 2048 f2 slots ----
        for (int slot = tid; slot < I_PER * KSC * 4 * PM; slot += NT) {
            int m  = slot & 63;
            int q  = (slot >> 6) & 3;
            int s  = (slot >> 8) & 3;
            int iv = slot >> 10;
            int sg = c * KSC + s;
            const uint2 kf = *(const uint2*)(g_kh + (size_t)sg * 272 + q * 68 + m);
            const float2 vf = *(const float2*)(dynsmem + (size_t)(iv * 192 + sg * 4 + q) * 8);
            uint2 o;
            o.x = hmul2(kf.x, __float_as_uint(vf.x));
            o.y = hmul2(kf.y, __float_as_uint(vf.y));
            *(uint2*)(dynsmem + (size_t)(BP_OFF + iv * BP_II + s * SLICE_B + q * 544 + m * 8)) = o;
        }
        __syncthreads();                            // B'(c) ready

        const char* stg = dynsmem + V1T + (c % NS) * STG_V2;
        const char* bpp = dynsmem + bpo;

#pragma unroll
        for (int ks = 0; ks < KSC; ks++) {
            // A fragments: raw v2 fp16, one LDS.128 per j16 subtile
            const float4 va0 = *(const float4*)(stg + aoff + ks * 64);
            const float4 va1 = *(const float4*)(stg + aoff + 8 * PRSTR + ks * 64);
            const uint32_t A0[4] = { __float_as_uint(va0.x), __float_as_uint(va0.y),
                                     __float_as_uint(va0.z), __float_as_uint(va0.w) };
            const uint32_t A1[4] = { __float_as_uint(va1.x), __float_as_uint(va1.y),
                                     __float_as_uint(va1.z), __float_as_uint(va1.w) };

            const char* bb = bpp + ks * SLICE_B;
#pragma unroll
            for (int nt = 0; nt < 8; nt++) {
                const uint2 bf = *(const uint2*)(bb + nt * 64);
#define DO_MMA(ACC, AR)                                                         \
                asm volatile(                                                   \
                    "mma.sync.aligned.m16n8k16.row.col.f32.f16.f16.f32 "       \
                    "{%0,%1,%2,%3}, {%4,%5,%6,%7}, {%8,%9}, {%0,%1,%2,%3};"    \
                    : "+f"(ACC[0]), "+f"(ACC[1]), "+f"(ACC[2]), "+f"(ACC[3])   \
                    : "r"(AR[0]), "r"(AR[1]), "r"(AR[2]), "r"(AR[3]),          \
                      "r"(bf.x), "r"(bf.y))
                DO_MMA(acc[0][nt], A0);
                DO_MMA(acc[1][nt], A1);
#undef DO_MMA
            }
        }
    }

    // ---- epilogue: tanh + store ----
    float* ob = out + ((size_t)(b * PT1 + i0 + ii) * PT2) * PM;
#pragma unroll
    for (int jsub = 0; jsub < 2; jsub++) {
        const int jr = j5 * 32 + jsub * 16 + qrow;
#pragma unroll
        for (int nt = 0; nt < 8; nt++) {
            const int col = nt * 8 + 2 * qc;
            float2 r0, r1;
            r0.x = fast_tanh(acc[jsub][nt][0]);
            r0.y = fast_tanh(acc[jsub][nt][1]);
            r1.x = fast_tanh(acc[jsub][nt][2]);
            r1.y = fast_tanh(acc[jsub][nt][3]);
            *(float2*)(ob + (size_t)jr * PM + col)       = r0;
            *(float2*)(ob + (size_t)(jr + 8) * PM + col) = r1;
        }
    }
}

extern "C" void kernel_launch(void* const* d_in, const int* in_sizes, int n_in,
                              void* d_out, int out_size)
{
    const float* v1 = nullptr;
    const float* v2 = nullptr;
    const float* kern = nullptr;
    for (int idx = 0; idx < n_in; idx++) {
        if (in_sizes[idx] == PB * PT1 * PD)      v1   = (const float*)d_in[idx];
        else if (in_sizes[idx] == PB * PT2 * PD) v2   = (const float*)d_in[idx];
        else if (in_sizes[idx] == PM * PD)       kern = (const float*)d_in[idx];
    }
    float* out = (float*)d_out;

    prep_all<<<(V2HN + KHN + 255) / 256, 256>>>(v2, kern);

    cudaFuncSetAttribute(mpcos_main, cudaFuncAttributeMaxDynamicSharedMemorySize, SMEM_TOTAL);
    dim3 grid(PT1 / I_PER, PB);   // (64, 64)
    mpcos_main<<<grid, NT, SMEM_TOTAL>>>(v1, out);
}

// round 14
// speedup vs baseline: 2.0303x; 2.0303x over previous
#include <cuda_runtime.h>
#include <cuda_fp16.h>
#include <cstdint>

// out[b,i,j,m] = tanh( sum_d v1[b,i,d] * kernel[m,d] * v2[b,j,d] )
#define PB   64
#define PT1  128
#define PT2  160
#define PD   768
#define PM   64

#define NS16     48                   // 16-wide k-slices total
#define KSC      4                    // slices per chunk (K=64)
#define NCHUNK   (NS16 / KSC)         // 12
#define NS       3                    // pipeline stages
#define NT       320                  // 10 warps
#define I_PER    2

#define PRSTR    320                  // v2 pair-row stride (256B data + 64B pad; conflict-free LDS.128)
#define STGV2    (40 * PRSTR)         // 12800 (40 pair-rows = one j-half)
#define SLICE_B  2176                 // kern bytes per k16 slice (4 qc x 544)
#define STGKP    (KSC * SLICE_B)      // 8704
#define STGB     (STGV2 + STGKP)      // 21504
#define V1T      3072                 // v1 table: 2 ii x 192 float2
#define SMEM_TOTAL (V1T + NS * STGB)  // 67584  (x3 CTAs = 202752 <= 228KB)

#define V2HN (PB * 80 * NS16 * 4)     // 983040 float4 entries
#define KHN  (NS16 * 4 * PM)          // 12288 float2 slots

// ---- device-global fp16-prepped operands (layouts unchanged from R10) ----
// g_v2h[((b*80+pr)*48+s)*4+qc] = {h2(v2[j][d0],v2[j][d0+1]), h2(v2[j8][..]),
//                                 h2(v2[j][d0+8],..), h2(v2[j8][d0+8],..)}
//   j = (pr>>3)*16 + (pr&7), j8 = j+8, d0 = s*16 + 2*qc
__device__ __align__(16) float4 g_v2h[V2HN];
// g_kh[s*272 + qc*68 + m] = {h2(k[m][d0],k[m][d0+1]), h2(k[m][d0+8],k[m][d0+9])}
__device__ __align__(16) float2 g_kh[NS16 * 272];

__device__ __forceinline__ float fast_tanh(float x) {
    float ax = fabsf(x);
    float e  = __expf(-2.0f * ax);
    float r  = __fdividef(1.0f - e, 1.0f + e);
    return copysignf(r, x);
}
__device__ __forceinline__ uint32_t s2u(const void* p) {
    uint32_t a;
    asm("{ .reg .u64 t; cvta.to.shared.u64 t, %1; cvt.u32.u64 %0, t; }" : "=r"(a) : "l"(p));
    return a;
}
__device__ __forceinline__ void cpa16(uint32_t dst, const void* src) {
    asm volatile("cp.async.cg.shared.global [%0], [%1], 16;" :: "r"(dst), "l"(src));
}
__device__ __forceinline__ uint32_t h2pack(float x, float y) {
    __half2 h = __floats2half2_rn(x, y);
    return *(uint32_t*)&h;
}
__device__ __forceinline__ uint32_t hmul2(uint32_t a, uint32_t b) {
    uint32_t d;
    asm("mul.rn.f16x2 %0, %1, %2;" : "=r"(d) : "r"(a), "r"(b));
    return d;
}

// ---- prep: fp16-convert + permute v2 and kernel (unchanged from R10) ----
__global__ void prep_all(const float* __restrict__ v2, const float* __restrict__ kern) {
    int t = blockIdx.x * blockDim.x + threadIdx.x;
    if (t < V2HN) {
        int qc = t & 3;
        int t2 = t >> 2;
        int s  = t2 % NS16;
        int pr = (t2 / NS16) % 80;
        int b  = t2 / (NS16 * 80);
        int j  = (pr >> 3) * 16 + (pr & 7);
        int d0 = s * 16 + 2 * qc;
        const float* p0 = v2 + ((size_t)(b * PT2 + j) * PD + d0);
        const float* p8 = p0 + 8 * PD;
        float4 o;
        o.x = __uint_as_float(h2pack(p0[0], p0[1]));
        o.y = __uint_as_float(h2pack(p8[0], p8[1]));
        o.z = __uint_as_float(h2pack(p0[8], p0[9]));
        o.w = __uint_as_float(h2pack(p8[8], p8[9]));
        g_v2h[t] = o;
    } else if (t < V2HN + KHN) {
        int u  = t - V2HN;
        int m  = u & 63;
        int qc = (u >> 6) & 3;
        int s  = u >> 8;
        int d0 = s * 16 + 2 * qc;
        const float* kp = kern + (size_t)m * PD + d0;
        float2 o;
        o.x = __uint_as_float(h2pack(kp[0], kp[1]));
        o.y = __uint_as_float(h2pack(kp[8], kp[9]));
        g_kh[s * 272 + qc * 68 + m] = o;
    }
}

extern __shared__ char dynsmem[];

// stage one chunk: v2 j-half (40 pair-rows x 16 f4 = 640) + kern (544 x 16B)
__device__ __forceinline__ void prefetch_stage(uint32_t stg, int b, int h, int s0, int tid) {
#pragma unroll
    for (int it = 0; it < 2; it++) {               // 640 = 2 * NT
        int t = tid + it * NT;
        int p = t >> 4, r = t & 15;                // r = sp*4 + qc
        cpa16(stg + p * PRSTR + r * 16,
              g_v2h + (((size_t)b * 80 + 40 * h + p) * NS16 + s0 + (r >> 2)) * 4 + (r & 3));
    }
#pragma unroll
    for (int it = 0; it < 2; it++) {               // 544 x 16B (2nd iter partial)
        int t = tid + it * NT;
        if (t < STGKP / 16)
            cpa16(stg + STGV2 + t * 16, (const char*)g_kh + (size_t)s0 * SLICE_B + t * 16);
    }
}

__global__ __launch_bounds__(NT, 3)
void mpcos_main(const float* __restrict__ v1, float* __restrict__ out)
{
    const uint32_t sb = s2u(dynsmem);
    const int tid  = threadIdx.x;
    const int w    = tid >> 5, lane = tid & 31;
    const int qrow = lane >> 2, qc = lane & 3;
    const int mw   = w / 5, t5 = w % 5;            // m-half (32 cols), j16 tile within j-half
    const int bx   = blockIdx.x;
    const int b    = blockIdx.y;
    const int i0   = (bx >> 1) * I_PER;
    const int h    = bx & 1;                       // j-half: rows [80h, 80h+80)

    const float* v1b = v1 + ((size_t)b * PT1 + i0) * PD;

    // ---- v1 fp16 pair table: slot = iv*192 + s*4 + q (STRIDED: 384 > NT) ----
    for (int t = tid; t < I_PER * 192; t += NT) {
        int iv = (t >= 192) ? 1 : 0;
        int r  = t - iv * 192;
        int s  = r >> 2, q = r & 3;
        int d0 = s * 16 + 2 * q;
        const float* vp = v1b + (size_t)iv * PD + d0;
        float2 o;
        o.x = __uint_as_float(h2pack(vp[0], vp[1]));
        o.y = __uint_as_float(h2pack(vp[8], vp[9]));
        *(float2*)(dynsmem + (size_t)t * 8) = o;
    }

    prefetch_stage(sb + V1T, b, h, 0, tid);
    asm volatile("cp.async.commit_group;" ::: "memory");
    prefetch_stage(sb + V1T + STGB, b, h, KSC, tid);
    asm volatile("cp.async.commit_group;" ::: "memory");

    float acc[I_PER][4][4] = {};                   // [ii][nt][4]  -> 32 regs

    const uint32_t aoff = (uint32_t)((t5 * 8 + qrow) * PRSTR + qc * 16);
    const uint32_t boff = (uint32_t)(STGV2 + qc * 544 + (mw * 32 + qrow) * 8);

    for (int c = 0; c < NCHUNK; c++) {
        if (c < NCHUNK - 1)
            asm volatile("cp.async.wait_group 1;" ::: "memory");
        else
            asm volatile("cp.async.wait_group 0;" ::: "memory");
        __syncthreads();

        if (c + 2 < NCHUNK) {
            prefetch_stage(sb + V1T + ((c + 2) % NS) * STGB, b, h, (c + 2) * KSC, tid);
            asm volatile("cp.async.commit_group;" ::: "memory");
        }

        const char* stg = dynsmem + V1T + (c % NS) * STGB;
        const int vslot = c * 16 + qc;             // f2 slot base into v1 table

#pragma unroll
        for (int ks = 0; ks < KSC; ks++) {
            // A fragment: raw v2 fp16, one LDS.128
            const float4 va = *(const float4*)(stg + aoff + ks * 64);
            // v1 pairs (broadcast LDS.64) for both i's
            const float2 p0 = *(const float2*)(dynsmem + (size_t)(vslot + ks * 4) * 8);
            const float2 p1 = *(const float2*)(dynsmem + (size_t)(192 + vslot + ks * 4) * 8);

            uint32_t A0[4], A1[4];
            A0[0] = hmul2(__float_as_uint(va.x), __float_as_uint(p0.x));
            A0[1] = hmul2(__float_as_uint(va.y), __float_as_uint(p0.x));
            A0[2] = hmul2(__float_as_uint(va.z), __float_as_uint(p0.y));
            A0[3] = hmul2(__float_as_uint(va.w), __float_as_uint(p0.y));
            A1[0] = hmul2(__float_as_uint(va.x), __float_as_uint(p1.x));
            A1[1] = hmul2(__float_as_uint(va.y), __float_as_uint(p1.x));
            A1[2] = hmul2(__float_as_uint(va.z), __float_as_uint(p1.y));
            A1[3] = hmul2(__float_as_uint(va.w), __float_as_uint(p1.y));

            const char* bb = stg + boff + ks * SLICE_B;
#pragma unroll
            for (int nt = 0; nt < 4; nt++) {
                const uint2 bf = *(const uint2*)(bb + nt * 64);   // B reused across ii
#define DO_MMA(ACC, AR)                                                         \
                asm volatile(                                                   \
                    "mma.sync.aligned.m16n8k16.row.col.f32.f16.f16.f32 "       \
                    "{%0,%1,%2,%3}, {%4,%5,%6,%7}, {%8,%9}, {%0,%1,%2,%3};"    \
                    : "+f"(ACC[0]), "+f"(ACC[1]), "+f"(ACC[2]), "+f"(ACC[3])   \
                    : "r"(AR[0]), "r"(AR[1]), "r"(AR[2]), "r"(AR[3]),          \
                      "r"(bf.x), "r"(bf.y))
                DO_MMA(acc[0][nt], A0);
                DO_MMA(acc[1][nt], A1);
#undef DO_MMA
            }
        }
    }

    // ---- epilogue: tanh + store ----
    const int jr = (5 * h + t5) * 16 + qrow;
#pragma unroll
    for (int ii = 0; ii < I_PER; ii++) {
        float* ob = out + ((size_t)(b * PT1 + i0 + ii) * PT2) * PM;
#pragma unroll
        for (int nt = 0; nt < 4; nt++) {
            const int col = mw * 32 + nt * 8 + 2 * qc;
            float2 r0, r1;
            r0.x = fast_tanh(acc[ii][nt][0]);
            r0.y = fast_tanh(acc[ii][nt][1]);
            r1.x = fast_tanh(acc[ii][nt][2]);
            r1.y = fast_tanh(acc[ii][nt][3]);
            *(float2*)(ob + (size_t)jr * PM + col)       = r0;
            *(float2*)(ob + (size_t)(jr + 8) * PM + col) = r1;
        }
    }
}

extern "C" void kernel_launch(void* const* d_in, const int* in_sizes, int n_in,
                              void* d_out, int out_size)
{
    const float* v1 = nullptr;
    const float* v2 = nullptr;
    const float* kern = nullptr;
    for (int idx = 0; idx < n_in; idx++) {
        if (in_sizes[idx] == PB * PT1 * PD)      v1   = (const float*)d_in[idx];
        else if (in_sizes[idx] == PB * PT2 * PD) v2   = (const float*)d_in[idx];
        else if (in_sizes[idx] == PM * PD)       kern = (const float*)d_in[idx];
    }
    float* out = (float*)d_out;

    prep_all<<<(V2HN + KHN + 255) / 256, 256>>>(v2, kern);

    cudaFuncSetAttribute(mpcos_main, cudaFuncAttributeMaxDynamicSharedMemorySize, SMEM_TOTAL);
    dim3 grid(2 * (PT1 / I_PER), PB);   // (128, 64): x = i-group * 2 + j-half
    mpcos_main<<<grid, NT, SMEM_TOTAL>>>(v1, out);
}

// round 16
// speedup vs baseline: 2.0505x; 1.0100x over previous
#include <cuda_runtime.h>
#include <cuda_fp16.h>
#include <cstdint>

// out[b,i,j,m] = tanh( sum_d v1[b,i,d] * kernel[m,d] * v2[b,j,d] )
#define PB   64
#define PT1  128
#define PT2  160
#define PD   768
#define PM   64

#define NS16     48                   // 16-wide k-slices total
#define KSC      4                    // slices per chunk (K=64)
#define NCHUNK   (NS16 / KSC)         // 12
#define NS       3                    // pipeline stages
#define NT       320                  // 10 warps
#define I_PER    2

#define PRSTR    320                  // v2 pair-row stride (256B data + 64B pad; conflict-free LDS.128)
#define STGV2    (40 * PRSTR)         // 12800 (40 pair-rows = one j-half)
#define SLICE_B  2176                 // kern bytes per k16 slice (4 qc x 544)
#define STGKP    (KSC * SLICE_B)      // 8704
#define STGB     (STGV2 + STGKP)      // 21504
#define V1T      3072                 // v1 table: 2 ii x 192 float2
#define SMEM_TOTAL (V1T + NS * STGB)  // 67584  (x3 CTAs = 202752 <= 228KB)

#define V2HN (PB * 80 * NS16 * 4)     // 983040 float4 entries
#define KHN  (NS16 * 4 * PM)          // 12288 float2 slots

// ---- device-global fp16-prepped operands (layouts unchanged from R10/R14) ----
// g_v2h[((b*80+pr)*48+s)*4+qc] = {h2(v2[j][d0],v2[j][d0+1]), h2(v2[j8][..]),
//                                 h2(v2[j][d0+8],..), h2(v2[j8][d0+8],..)}
//   j = (pr>>3)*16 + (pr&7), j8 = j+8, d0 = s*16 + 2*qc
__device__ __align__(16) float4 g_v2h[V2HN];
// g_kh[s*272 + qc*68 + m] = {h2(k[m][d0],k[m][d0+1]), h2(k[m][d0+8],k[m][d0+9])}
__device__ __align__(16) float2 g_kh[NS16 * 272];

__device__ __forceinline__ float tanh_mufu(float x) {
    float r;
    asm("tanh.approx.f32 %0, %1;" : "=f"(r) : "f"(x));   // MUFU.TANH, 1 op vs exp+rcp
    return r;
}
__device__ __forceinline__ uint32_t s2u(const void* p) {
    uint32_t a;
    asm("{ .reg .u64 t; cvta.to.shared.u64 t, %1; cvt.u32.u64 %0, t; }" : "=r"(a) : "l"(p));
    return a;
}
__device__ __forceinline__ void cpa16(uint32_t dst, const void* src) {
    asm volatile("cp.async.cg.shared.global [%0], [%1], 16;" :: "r"(dst), "l"(src));
}
__device__ __forceinline__ uint32_t h2pack(float x, float y) {
    __half2 h = __floats2half2_rn(x, y);
    return *(uint32_t*)&h;
}
__device__ __forceinline__ uint32_t hmul2(uint32_t a, uint32_t b) {
    uint32_t d;
    asm("mul.rn.f16x2 %0, %1, %2;" : "=r"(d) : "r"(a), "r"(b));
    return d;
}

// ---- prep: fp16-convert + permute v2 and kernel (unchanged) ----
__global__ void prep_all(const float* __restrict__ v2, const float* __restrict__ kern) {
    int t = blockIdx.x * blockDim.x + threadIdx.x;
    if (t < V2HN) {
        int qc = t & 3;
        int t2 = t >> 2;
        int s  = t2 % NS16;
        int pr = (t2 / NS16) % 80;
        int b  = t2 / (NS16 * 80);
        int j  = (pr >> 3) * 16 + (pr & 7);
        int d0 = s * 16 + 2 * qc;
        const float* p0 = v2 + ((size_t)(b * PT2 + j) * PD + d0);
        const float* p8 = p0 + 8 * PD;
        float4 o;
        o.x = __uint_as_float(h2pack(p0[0], p0[1]));
        o.y = __uint_as_float(h2pack(p8[0], p8[1]));
        o.z = __uint_as_float(h2pack(p0[8], p0[9]));
        o.w = __uint_as_float(h2pack(p8[8], p8[9]));
        g_v2h[t] = o;
    } else if (t < V2HN + KHN) {
        int u  = t - V2HN;
        int m  = u & 63;
        int qc = (u >> 6) & 3;
        int s  = u >> 8;
        int d0 = s * 16 + 2 * qc;
        const float* kp = kern + (size_t)m * PD + d0;
        float2 o;
        o.x = __uint_as_float(h2pack(kp[0], kp[1]));
        o.y = __uint_as_float(h2pack(kp[8], kp[9]));
        g_kh[s * 272 + qc * 68 + m] = o;
    }
}

extern __shared__ char dynsmem[];

// stage one chunk: v2 j-half (40 pair-rows x 16 f4 = 640) + kern (544 x 16B)
__device__ __forceinline__ void prefetch_stage(uint32_t stg, int b, int h, int s0, int tid) {
#pragma unroll
    for (int it = 0; it < 2; it++) {               // 640 = 2 * NT
        int t = tid + it * NT;
        int p = t >> 4, r = t & 15;                // r = sp*4 + qc
        cpa16(stg + p * PRSTR + r * 16,
              g_v2h + (((size_t)b * 80 + 40 * h + p) * NS16 + s0 + (r >> 2)) * 4 + (r & 3));
    }
#pragma unroll
    for (int it = 0; it < 2; it++) {               // 544 x 16B (2nd iter partial)
        int t = tid + it * NT;
        if (t < STGKP / 16)
            cpa16(stg + STGV2 + t * 16, (const char*)g_kh + (size_t)s0 * SLICE_B + t * 16);
    }
}

__global__ __launch_bounds__(NT, 3)
void mpcos_main(const float* __restrict__ v1, float* __restrict__ out)
{
    const uint32_t sb = s2u(dynsmem);
    const int tid  = threadIdx.x;
    const int w    = tid >> 5, lane = tid & 31;
    const int qrow = lane >> 2, qc = lane & 3;
    const int mw   = w / 5, t5 = w % 5;            // m-half (32 cols), j16 tile within j-half
    const int bx   = blockIdx.x;
    const int b    = blockIdx.y;
    const int i0   = (bx >> 1) * I_PER;
    const int h    = bx & 1;                       // j-half: rows [80h, 80h+80)

    const float* v1b = v1 + ((size_t)b * PT1 + i0) * PD;

    // ---- v1 fp16 pair table: slot = iv*192 + s*4 + q (STRIDED: 384 > NT) ----
    for (int t = tid; t < I_PER * 192; t += NT) {
        int iv = (t >= 192) ? 1 : 0;
        int r  = t - iv * 192;
        int s  = r >> 2, q = r & 3;
        int d0 = s * 16 + 2 * q;
        const float* vp = v1b + (size_t)iv * PD + d0;
        float2 o;
        o.x = __uint_as_float(h2pack(vp[0], vp[1]));
        o.y = __uint_as_float(h2pack(vp[8], vp[9]));
        *(float2*)(dynsmem + (size_t)t * 8) = o;
    }

    prefetch_stage(sb + V1T, b, h, 0, tid);
    asm volatile("cp.async.commit_group;" ::: "memory");
    prefetch_stage(sb + V1T + STGB, b, h, KSC, tid);
    asm volatile("cp.async.commit_group;" ::: "memory");

    float acc[I_PER][4][4] = {};                   // [ii][nt][4]  -> 32 regs

    const uint32_t aoff = (uint32_t)((t5 * 8 + qrow) * PRSTR + qc * 16);
    const uint32_t boff = (uint32_t)(STGV2 + qc * 544 + (mw * 32 + qrow) * 8);

    for (int c = 0; c < NCHUNK; c++) {
        if (c < NCHUNK - 1)
            asm volatile("cp.async.wait_group 1;" ::: "memory");
        else
            asm volatile("cp.async.wait_group 0;" ::: "memory");
        __syncthreads();

        if (c + 2 < NCHUNK) {
            prefetch_stage(sb + V1T + ((c + 2) % NS) * STGB, b, h, (c + 2) * KSC, tid);
            asm volatile("cp.async.commit_group;" ::: "memory");
        }

        const char* stg = dynsmem + V1T + (c % NS) * STGB;
        const int vslot = c * 16 + qc;             // f2 slot base into v1 table

#pragma unroll
        for (int ks = 0; ks < KSC; ks++) {
            // A fragment: raw v2 fp16, one LDS.128
            const float4 va = *(const float4*)(stg + aoff + ks * 64);
            // v1 pairs (broadcast LDS.64) for both i's
            const float2 p0 = *(const float2*)(dynsmem + (size_t)(vslot + ks * 4) * 8);
            const float2 p1 = *(const float2*)(dynsmem + (size_t)(192 + vslot + ks * 4) * 8);

            uint32_t A0[4], A1[4];
            A0[0] = hmul2(__float_as_uint(va.x), __float_as_uint(p0.x));
            A0[1] = hmul2(__float_as_uint(va.y), __float_as_uint(p0.x));
            A0[2] = hmul2(__float_as_uint(va.z), __float_as_uint(p0.y));
            A0[3] = hmul2(__float_as_uint(va.w), __float_as_uint(p0.y));
            A1[0] = hmul2(__float_as_uint(va.x), __float_as_uint(p1.x));
            A1[1] = hmul2(__float_as_uint(va.y), __float_as_uint(p1.x));
            A1[2] = hmul2(__float_as_uint(va.z), __float_as_uint(p1.y));
            A1[3] = hmul2(__float_as_uint(va.w), __float_as_uint(p1.y));

            const char* bb = stg + boff + ks * SLICE_B;
#pragma unroll
            for (int nt = 0; nt < 4; nt++) {
                const uint2 bf = *(const uint2*)(bb + nt * 64);   // B reused across ii
#define DO_MMA(ACC, AR)                                                         \
                asm volatile(                                                   \
                    "mma.sync.aligned.m16n8k16.row.col.f32.f16.f16.f32 "       \
                    "{%0,%1,%2,%3}, {%4,%5,%6,%7}, {%8,%9}, {%0,%1,%2,%3};"    \
                    : "+f"(ACC[0]), "+f"(ACC[1]), "+f"(ACC[2]), "+f"(ACC[3])   \
                    : "r"(AR[0]), "r"(AR[1]), "r"(AR[2]), "r"(AR[3]),          \
                      "r"(bf.x), "r"(bf.y))
                DO_MMA(acc[0][nt], A0);
                DO_MMA(acc[1][nt], A1);
#undef DO_MMA
            }
        }
    }

    // ---- epilogue: MUFU.TANH + store ----
    const int jr = (5 * h + t5) * 16 + qrow;
#pragma unroll
    for (int ii = 0; ii < I_PER; ii++) {
        float* ob = out + ((size_t)(b * PT1 + i0 + ii) * PT2) * PM;
#pragma unroll
        for (int nt = 0; nt < 4; nt++) {
            const int col = mw * 32 + nt * 8 + 2 * qc;
            float2 r0, r1;
            r0.x = tanh_mufu(acc[ii][nt][0]);
            r0.y = tanh_mufu(acc[ii][nt][1]);
            r1.x = tanh_mufu(acc[ii][nt][2]);
            r1.y = tanh_mufu(acc[ii][nt][3]);
            *(float2*)(ob + (size_t)jr * PM + col)       = r0;
            *(float2*)(ob + (size_t)(jr + 8) * PM + col) = r1;
        }
    }
}

extern "C" void kernel_launch(void* const* d_in, const int* in_sizes, int n_in,
                              void* d_out, int out_size)
{
    const float* v1 = nullptr;
    const float* v2 = nullptr;
    const float* kern = nullptr;
    for (int idx = 0; idx < n_in; idx++) {
        if (in_sizes[idx] == PB * PT1 * PD)      v1   = (const float*)d_in[idx];
        else if (in_sizes[idx] == PB * PT2 * PD) v2   = (const float*)d_in[idx];
        else if (in_sizes[idx] == PM * PD)       kern = (const float*)d_in[idx];
    }
    float* out = (float*)d_out;

    prep_all<<<(V2HN + KHN + 255) / 256, 256>>>(v2, kern);

    cudaFuncSetAttribute(mpcos_main, cudaFuncAttributeMaxDynamicSharedMemorySize, SMEM_TOTAL);
    dim3 grid(2 * (PT1 / I_PER), PB);   // (128, 64): x = i-group * 2 + j-half
    mpcos_main<<<grid, NT, SMEM_TOTAL>>>(v1, out);
}